// round 5
// baseline (speedup 1.0000x reference)
#include <cuda_runtime.h>
#include <math.h>

#define BATCH 4
#define NPTS  8192
#define NCLOUD 8                 // clouds 0-3 = pred batches, 4-7 = label batches
#define G     32
#define GC    (G * G * G)        // 32768 cells
#define GMIN  (-5.0f)
#define CELL  0.3125f            // 10 / 32
#define INV_CELL 3.2f
#define QTHREADS 256
#define QBLOCKS  ((NCLOUD * NPTS) / QTHREADS)   // 256

__device__ int    g_count[NCLOUD][GC];
__device__ int    g_fill [NCLOUD][GC];
__device__ int    g_start[NCLOUD][GC];
__device__ float4 g_pts  [NCLOUD][NPTS];
__device__ float  g_bsum [QBLOCKS];
__device__ unsigned g_counter = 0;

__device__ __forceinline__ int cell_coord(float v) {
    int c = (int)floorf((v - GMIN) * INV_CELL);
    return min(max(c, 0), G - 1);
}

// ---- K1: zero counts + fill cursors ----
__global__ void k_zero() {
    const int idx = blockIdx.x * 256 + threadIdx.x;
    if (idx < NCLOUD * GC) {
        ((int*)g_count)[idx] = 0;
        ((int*)g_fill)[idx]  = 0;
    }
}

// ---- K2: histogram points into cells ----
__global__ void k_count(const float* __restrict__ pred,
                        const float* __restrict__ label) {
    const int idx = blockIdx.x * 256 + threadIdx.x;      // 0 .. 65535
    const int c = idx >> 13;
    const int j = idx & (NPTS - 1);
    const float* p = ((c < 4) ? pred : label) + ((size_t)(c & 3) * NPTS + j) * 3;
    const int cx = cell_coord(p[0]);
    const int cy = cell_coord(p[1]);
    const int cz = cell_coord(p[2]);
    atomicAdd(&g_count[c][(cz * G + cy) * G + cx], 1);
}

// ---- K3: exclusive scan per cloud (one block per cloud) ----
__global__ __launch_bounds__(1024)
void k_scan() {
    const int c = blockIdx.x;
    const int t = threadIdx.x;
    __shared__ int s[1024];

    int sum = 0;
    int local[32];
    #pragma unroll
    for (int i = 0; i < 32; i++) {
        local[i] = g_count[c][t * 32 + i];
        sum += local[i];
    }
    s[t] = sum;
    __syncthreads();
    // Hillis-Steele inclusive scan over 1024 per-thread sums
    for (int off = 1; off < 1024; off <<= 1) {
        int add = (t >= off) ? s[t - off] : 0;
        __syncthreads();
        s[t] += add;
        __syncthreads();
    }
    int prefix = s[t] - sum;   // exclusive
    #pragma unroll
    for (int i = 0; i < 32; i++) {
        g_start[c][t * 32 + i] = prefix;
        prefix += local[i];
    }
}

// ---- K4: scatter points into cell-sorted order ----
__global__ void k_scatter(const float* __restrict__ pred,
                          const float* __restrict__ label) {
    const int idx = blockIdx.x * 256 + threadIdx.x;
    const int c = idx >> 13;
    const int j = idx & (NPTS - 1);
    const float* p = ((c < 4) ? pred : label) + ((size_t)(c & 3) * NPTS + j) * 3;
    const float x = p[0], y = p[1], z = p[2];
    const int cx = cell_coord(x);
    const int cy = cell_coord(y);
    const int cz = cell_coord(z);
    const int cell = (cz * G + cy) * G + cx;
    const int pos = g_start[c][cell] + atomicAdd(&g_fill[c][cell], 1);
    g_pts[c][pos] = make_float4(x, y, z, 0.0f);
}

// ---- K5: exact NN query via ring expansion + global reduce ----
__global__ __launch_bounds__(QTHREADS)
void k_query(float* __restrict__ out) {
    const int idx = blockIdx.x * QTHREADS + threadIdx.x;   // 0 .. 65535
    const int c  = idx >> 13;
    const int j  = idx & (NPTS - 1);
    const int tc = c ^ 4;                                   // opposite cloud, same batch

    const float4 q = g_pts[c][j];                           // sorted -> warp-coherent
    const int cx = cell_coord(q.x);
    const int cy = cell_coord(q.y);
    const int cz = cell_coord(q.z);

    const int* __restrict__ tstart = g_start[tc];
    const int* __restrict__ tcount = g_count[tc];
    const float4* __restrict__ tpts = g_pts[tc];

    float best = 3.0e38f;   // squared distance

    for (int r = 0; r < G; r++) {
        const int x0 = max(cx - r, 0), x1 = min(cx + r, G - 1);
        const int y0 = max(cy - r, 0), y1 = min(cy + r, G - 1);
        const int z0 = max(cz - r, 0), z1 = min(cz + r, G - 1);
        for (int z = z0; z <= z1; z++) {
            const int adz = abs(z - cz);
            for (int y = y0; y <= y1; y++) {
                const int ady = abs(y - cy);
                const bool face_zy = (adz == r) || (ady == r);
                for (int x = x0; x <= x1; x++) {
                    // only cells on the ring shell (chebyshev == r)
                    if (!face_zy && abs(x - cx) != r) continue;
                    const int cell = (z * G + y) * G + x;
                    const int n = tcount[cell];
                    if (n == 0) continue;
                    const int s0 = tstart[cell];
                    for (int k = 0; k < n; k++) {
                        const float4 p = tpts[s0 + k];
                        const float dx = q.x - p.x;
                        const float dy = q.y - p.y;
                        const float dz = q.z - p.z;
                        const float d2 = fmaf(dx, dx, fmaf(dy, dy, dz * dz));
                        best = fminf(best, d2);
                    }
                }
            }
        }
        // Termination: searched box covers cells [c-r, c+r]. Any unsearched
        // point lies geometrically outside this box (outliers clamped into
        // boundary cells are outside any smaller box too), so the distance
        // from q to the box exterior is a valid lower bound.
        const float lbx = fminf(q.x - (GMIN + (float)(cx - r) * CELL),
                                (GMIN + (float)(cx + r + 1) * CELL) - q.x);
        const float lby = fminf(q.y - (GMIN + (float)(cy - r) * CELL),
                                (GMIN + (float)(cy + r + 1) * CELL) - q.y);
        const float lbz = fminf(q.z - (GMIN + (float)(cz - r) * CELL),
                                (GMIN + (float)(cz + r + 1) * CELL) - q.z);
        const float lb = fminf(lbx, fminf(lby, lbz));
        if (lb > 0.0f && best <= lb * lb) break;
    }

    float s = sqrtf(best);

    // Block reduction
    #pragma unroll
    for (int off = 16; off > 0; off >>= 1)
        s += __shfl_down_sync(0xFFFFFFFFu, s, off);

    __shared__ float warp_sums[QTHREADS / 32];
    __shared__ bool is_last;
    const int tid = threadIdx.x;
    if ((tid & 31) == 0) warp_sums[tid >> 5] = s;
    __syncthreads();
    if (tid == 0) {
        float bs = 0.0f;
        #pragma unroll
        for (int w = 0; w < QTHREADS / 32; w++) bs += warp_sums[w];
        g_bsum[blockIdx.x] = bs;
        __threadfence();
        const unsigned done = atomicAdd(&g_counter, 1u) + 1u;
        is_last = (done == QBLOCKS);
    }
    __syncthreads();

    if (is_last) {
        float v = g_bsum[tid];          // QTHREADS == QBLOCKS == 256
        #pragma unroll
        for (int off = 16; off > 0; off >>= 1)
            v += __shfl_down_sync(0xFFFFFFFFu, v, off);
        if ((tid & 31) == 0) warp_sums[tid >> 5] = v;
        __syncthreads();
        if (tid == 0) {
            float tot = 0.0f;
            #pragma unroll
            for (int w = 0; w < QTHREADS / 32; w++) tot += warp_sums[w];
            out[0] = tot * (1.0f / (float)(BATCH * NPTS));
            g_counter = 0u;             // reset for next graph replay
        }
    }
}

extern "C" void kernel_launch(void* const* d_in, const int* in_sizes, int n_in,
                              void* d_out, int out_size) {
    const float* pred  = (const float*)d_in[0];
    const float* label = (const float*)d_in[1];
    float* out = (float*)d_out;

    k_zero   <<<(NCLOUD * GC + 255) / 256, 256>>>();
    k_count  <<<(NCLOUD * NPTS) / 256, 256>>>(pred, label);
    k_scan   <<<NCLOUD, 1024>>>();
    k_scatter<<<(NCLOUD * NPTS) / 256, 256>>>(pred, label);
    k_query  <<<QBLOCKS, QTHREADS>>>(out);
}

// round 6
// speedup vs baseline: 4.0872x; 4.0872x over previous
#include <cuda_runtime.h>
#include <math.h>

#define BATCH 4
#define NPTS  8192
#define NSPLIT 16
#define BRANGE (NPTS / NSPLIT)            // 512 label cols per block
#define NPAIR  (BRANGE / 2)               // 256 packed col-pairs
#define PTS_PER_THREAD 8
#define THREADS 64
#define ROWS_PER_BLOCK (THREADS * PTS_PER_THREAD)  // 512
#define NCHUNK (NPTS / ROWS_PER_BLOCK)             // 16
#define FIN_THREADS 256
#define FIN_BLOCKS ((2 * BATCH * NPTS) / FIN_THREADS)  // 256

// Per-point running max of t' = -||x-y||^2/2, monotonic-uint encoded.
// Zero-init == -inf under the encoding (all real values encode > 0).
__device__ unsigned g_rmax[BATCH * NPTS];   // pred  -> label direction
__device__ unsigned g_cmax[BATCH * NPTS];   // label -> pred direction
__device__ float    g_bsum[FIN_BLOCKS];
__device__ unsigned g_counter = 0;

typedef unsigned long long ull;
union U64F2 { ull u; float2 f; };

__device__ __forceinline__ ull fma2(ull a, ull b, ull c) {
    ull d; asm("fma.rn.f32x2 %0, %1, %2, %3;" : "=l"(d) : "l"(a), "l"(b), "l"(c)); return d;
}
__device__ __forceinline__ ull pack2(float lo, float hi) {
    U64F2 u; u.f = make_float2(lo, hi); return u.u;
}
__device__ __forceinline__ float lof(ull v) { U64F2 u; u.u = v; return u.f.x; }
__device__ __forceinline__ float hif(ull v) { U64F2 u; u.u = v; return u.f.y; }

// Order-preserving float -> uint encoding (for atomicMax).
__device__ __forceinline__ unsigned enc(float f) {
    unsigned u = __float_as_uint(f);
    return u ^ ((unsigned)((int)u >> 31) | 0x80000000u);
}
__device__ __forceinline__ float dec(unsigned k) {
    unsigned u = (k & 0x80000000u) ? (k ^ 0x80000000u) : ~k;
    return __uint_as_float(u);
}

// One block: 512 pred rows x 512 label cols of one batch's -d^2/2 matrix.
// blockIdx.x = row chunk, blockIdx.y = batch, blockIdx.z = col split.
__global__ __launch_bounds__(THREADS)
void chamfer_main(const float* __restrict__ pred,
                  const float* __restrict__ label) {
    const int split = blockIdx.z;
    const int b     = blockIdx.y;
    const float* __restrict__ A  = pred  + (size_t)b * NPTS * 3;
    const float* __restrict__ Bt = label + (size_t)b * NPTS * 3
                                         + (size_t)split * BRANGE * 3;

    // Pair layout: slot 2q = (bx0,bx1,by0,by1), slot 2q+1 = (bz0,bz1,nwy0,nwy1)
    // where nwy = -0.5*||y||^2.
    __shared__ float4 sB[BRANGE];   // 8 KB

    const int tid = threadIdx.x;

    #pragma unroll
    for (int q = tid; q < NPAIR; q += THREADS) {
        const float* p = Bt + 6 * q;
        const float bx0 = p[0], by0 = p[1], bz0 = p[2];
        const float bx1 = p[3], by1 = p[4], bz1 = p[5];
        const float nwy0 = -0.5f * fmaf(bx0, bx0, fmaf(by0, by0, bz0 * bz0));
        const float nwy1 = -0.5f * fmaf(bx1, bx1, fmaf(by1, by1, bz1 * bz1));
        sB[2 * q]     = make_float4(bx0, bx1, by0, by1);
        sB[2 * q + 1] = make_float4(bz0, bz1, nwy0, nwy1);
    }

    // Per-thread pred rows: duplicated f32x2 coords + nwx = -0.5*||x||^2
    ull ax2[PTS_PER_THREAD], ay2[PTS_PER_THREAD], az2[PTS_PER_THREAD], nwx2[PTS_PER_THREAD];
    float m[PTS_PER_THREAD];
    const int row0 = blockIdx.x * ROWS_PER_BLOCK + tid;
    #pragma unroll
    for (int p = 0; p < PTS_PER_THREAD; p++) {
        const int i = row0 + p * THREADS;
        const float ax = A[i * 3 + 0];
        const float ay = A[i * 3 + 1];
        const float az = A[i * 3 + 2];
        const float nwx = -0.5f * fmaf(ax, ax, fmaf(ay, ay, az * az));
        ax2[p]  = pack2(ax, ax);
        ay2[p]  = pack2(ay, ay);
        az2[p]  = pack2(az, az);
        nwx2[p] = pack2(nwx, nwx);
        m[p] = -3.0e38f;
    }
    __syncthreads();

    const ulonglong2* __restrict__ sB64 = (const ulonglong2*)sB;
    const int lane = tid & 31;
    const size_t colbase = (size_t)b * NPTS + (size_t)split * BRANGE;
    const ull ONE2 = 0x3F8000003F800000ULL;   // (1.0f, 1.0f)

    #pragma unroll 2
    for (int q = 0; q < NPAIR; q++) {
        const ulonglong2 v0 = sB64[2 * q];       // (bx0,bx1) (by0,by1)
        const ulonglong2 v1 = sB64[2 * q + 1];   // (bz0,bz1) (nwy0,nwy1)
        float c0 = -3.0e38f, c1 = -3.0e38f;
        #pragma unroll
        for (int p = 0; p < PTS_PER_THREAD; p++) {
            ull t = fma2(v1.x, az2[p], v1.y);    // bz*az - y^2/2
            t = fma2(v0.y, ay2[p], t);           // + by*ay
            t = fma2(v0.x, ax2[p], t);           // + bx*ax
            t = fma2(ONE2, nwx2[p], t);          // - x^2/2   => -d^2/2
            const float tl = lof(t), th = hif(t);
            m[p] = fmaxf(m[p], fmaxf(tl, th));   // row side (both cols)
            c0 = fmaxf(c0, tl);                  // col side
            c1 = fmaxf(c1, th);
        }
        // Warp-reduce col maxes, lane 0 fires no-return global atomics.
        #pragma unroll
        for (int off = 16; off > 0; off >>= 1) {
            c0 = fmaxf(c0, __shfl_xor_sync(0xFFFFFFFFu, c0, off));
            c1 = fmaxf(c1, __shfl_xor_sync(0xFFFFFFFFu, c1, off));
        }
        if (lane == 0) {
            atomicMax(&g_cmax[colbase + 2 * q],     enc(c0));
            atomicMax(&g_cmax[colbase + 2 * q + 1], enc(c1));
        }
    }

    // Flush row maxes (one slot per pred point, merged across col splits).
    #pragma unroll
    for (int p = 0; p < PTS_PER_THREAD; p++) {
        atomicMax(&g_rmax[(size_t)b * NPTS + row0 + p * THREADS], enc(m[p]));
    }
}

// One thread per (dir, batch, point): decode max t' = -d^2/2, sqrt, reduce.
// Also resets the accumulators so graph replays are deterministic.
__global__ __launch_bounds__(FIN_THREADS)
void chamfer_finalize(float* __restrict__ out) {
    const int idx = blockIdx.x * FIN_THREADS + threadIdx.x;   // 0 .. 65535
    const int dir = idx >> 15;
    const int rem = idx & 32767;                               // b*NPTS + i
    unsigned* __restrict__ g = (dir == 0) ? g_rmax : g_cmax;

    const float m = dec(g[rem]);
    g[rem] = 0u;    // reset for next replay
    const float d = sqrtf(fmaxf(-2.0f * m, 0.0f));
    float s = d;

    #pragma unroll
    for (int off = 16; off > 0; off >>= 1)
        s += __shfl_down_sync(0xFFFFFFFFu, s, off);

    __shared__ float warp_sums[FIN_THREADS / 32];
    __shared__ bool is_last;
    const int tid = threadIdx.x;
    if ((tid & 31) == 0) warp_sums[tid >> 5] = s;
    __syncthreads();
    if (tid == 0) {
        float bs = 0.0f;
        #pragma unroll
        for (int w = 0; w < FIN_THREADS / 32; w++) bs += warp_sums[w];
        g_bsum[blockIdx.x] = bs;
        __threadfence();
        const unsigned done = atomicAdd(&g_counter, 1u) + 1u;
        is_last = (done == FIN_BLOCKS);
    }
    __syncthreads();

    if (is_last) {
        float v = g_bsum[tid];          // FIN_THREADS == FIN_BLOCKS == 256
        #pragma unroll
        for (int off = 16; off > 0; off >>= 1)
            v += __shfl_down_sync(0xFFFFFFFFu, v, off);
        if ((tid & 31) == 0) warp_sums[tid >> 5] = v;
        __syncthreads();
        if (tid == 0) {
            float tot = 0.0f;
            #pragma unroll
            for (int w = 0; w < FIN_THREADS / 32; w++) tot += warp_sums[w];
            out[0] = tot * (1.0f / (float)(BATCH * NPTS));
            g_counter = 0u;             // reset for next graph replay
        }
    }
}

extern "C" void kernel_launch(void* const* d_in, const int* in_sizes, int n_in,
                              void* d_out, int out_size) {
    const float* pred  = (const float*)d_in[0];
    const float* label = (const float*)d_in[1];
    float* out = (float*)d_out;

    dim3 grid(NCHUNK, BATCH, NSPLIT);   // 16 x 4 x 16 = 1024 blocks
    chamfer_main<<<grid, THREADS>>>(pred, label);
    chamfer_finalize<<<FIN_BLOCKS, FIN_THREADS>>>(out);
}